// round 2
// baseline (speedup 1.0000x reference)
#include <cuda_runtime.h>

namespace {
constexpr int B  = 2;
constexpr int N  = 2048;
constexpr int C  = 512;
constexpr int H  = 8;
constexpr int DH = 64;
constexpr int M  = B * N;          // 4096 tokens
constexpr int QKV_W = 3 * C * 2;   // 3072 weight rows
constexpr int QKV_O = 3 * C;       // 1536 fused outputs
constexpr int PRJ_W = C * 2;       // 1024 weight rows
constexpr int PRJ_O = C;           // 512 fused outputs
}

// Scratch (device globals — no allocation allowed)
__device__ float g_Wqkv[(size_t)QKV_W * C];      // normalized + pair-permuted
__device__ float g_Wprj[(size_t)PRJ_W * C];
__device__ float g_xnorm[M];
__device__ float g_qkv[(size_t)M * QKV_O];       // (b*n, [q|k|v] = 3*512)
__device__ float g_ao[(size_t)M * C];            // attention output (b*n, C)
__device__ float g_aonorm[M];

// ---------------------------------------------------------------------------
// Normalize weight rows and permute so that maxout pair partners (row o and
// row o+half) land at positions (g*32 + o%16) and (g*32 + o%16 + 16), g=o/16.
// This makes the maxout pair thread-local in the GEMM (thread cols tx+16*j).
// ---------------------------------------------------------------------------
__global__ void norm_w_kernel(const float* __restrict__ W,
                              float* __restrict__ dst, int half) {
    int r = blockIdx.x, t = threadIdx.x;
    const float* src = W + (size_t)r * C;
    float s = 0.f;
    for (int i = t; i < C; i += 128) { float v = src[i]; s += v * v; }
    #pragma unroll
    for (int o = 16; o; o >>= 1) s += __shfl_xor_sync(0xffffffffu, s, o);
    __shared__ float sm[4];
    if ((t & 31) == 0) sm[t >> 5] = s;
    __syncthreads();
    float inv = rsqrtf(sm[0] + sm[1] + sm[2] + sm[3]);
    int o = (r < half) ? r : r - half;
    int member = (r < half) ? 0 : 1;
    int dr = (o >> 4) * 32 + (o & 15) + member * 16;
    float* d = dst + (size_t)dr * C;
    for (int i = t; i < C; i += 128) d[i] = src[i] * inv;
}

__global__ void row_norm_kernel(const float* __restrict__ A,
                                float* __restrict__ out) {
    int r = blockIdx.x, t = threadIdx.x;
    const float* src = A + (size_t)r * C;
    float s = 0.f;
    for (int i = t; i < C; i += 128) { float v = src[i]; s += v * v; }
    #pragma unroll
    for (int o = 16; o; o >>= 1) s += __shfl_xor_sync(0xffffffffu, s, o);
    __shared__ float sm[4];
    if ((t & 31) == 0) sm[t >> 5] = s;
    __syncthreads();
    if (t == 0) out[r] = sqrtf(sm[0] + sm[1] + sm[2] + sm[3]);
}

// ---------------------------------------------------------------------------
// Fused Bcos GEMM: out[m][o] = f(max(dot(A[m], Wp[pos0]), dot(A[m], Wp[pos1])))
// f(v) = v*|v| / (norm[m]*sqrt(C)).  128x128x32 tiles, 256 thr, 8x8 microtile.
// ---------------------------------------------------------------------------
__global__ __launch_bounds__(256) void bcos_gemm_kernel(
    const float* __restrict__ A, const float* __restrict__ Wp,
    const float* __restrict__ norms, float* __restrict__ out, int nout)
{
    __shared__ float As[32][129];
    __shared__ float Ws[32][129];
    int tid = threadIdx.x;
    int tx = tid & 15, ty = tid >> 4;
    int bm = blockIdx.y * 128;
    int bc = blockIdx.x * 128;   // weight-row (permuted) offset

    float acc[8][8];
    #pragma unroll
    for (int i = 0; i < 8; i++)
        #pragma unroll
        for (int j = 0; j < 8; j++) acc[i][j] = 0.f;

    for (int k0 = 0; k0 < C; k0 += 32) {
        #pragma unroll
        for (int u = 0; u < 16; u++) {
            int idx = tid + u * 256;
            int rr = idx >> 5, kk = idx & 31;
            As[kk][rr] = A[(size_t)(bm + rr) * C + k0 + kk];
        }
        #pragma unroll
        for (int u = 0; u < 16; u++) {
            int idx = tid + u * 256;
            int rr = idx >> 5, kk = idx & 31;
            Ws[kk][rr] = Wp[(size_t)(bc + rr) * C + k0 + kk];
        }
        __syncthreads();

        #pragma unroll 8
        for (int kk = 0; kk < 32; kk++) {
            float a[8], w[8];
            #pragma unroll
            for (int i = 0; i < 8; i++) a[i] = As[kk][ty * 8 + i];
            #pragma unroll
            for (int j = 0; j < 8; j++) w[j] = Ws[kk][tx + 16 * j];
            #pragma unroll
            for (int i = 0; i < 8; i++)
                #pragma unroll
                for (int j = 0; j < 8; j++)
                    acc[i][j] = fmaf(a[i], w[j], acc[i][j]);
        }
        __syncthreads();
    }

    const float sc = rsqrtf((float)C);
    #pragma unroll
    for (int i = 0; i < 8; i++) {
        int m = bm + ty * 8 + i;
        float inv = sc / norms[m];
        #pragma unroll
        for (int jp = 0; jp < 4; jp++) {
            // cols (tx+16*(2jp)) and (tx+16*(2jp+1)) are maxout partners
            float v = fmaxf(acc[i][2 * jp], acc[i][2 * jp + 1]);
            out[(size_t)m * nout + (bc >> 1) + jp * 16 + tx] = v * fabsf(v) * inv;
        }
    }
}

// ---------------------------------------------------------------------------
// Flash attention, fp32. One block = one (b,h) x 64-query tile.
// 256 threads: thread (r = tid>>2, cg = tid&3) owns row r, 16-col group cg.
// Q and P live in registers; K/V tiles in smem.
// ---------------------------------------------------------------------------
__global__ __launch_bounds__(256) void attn_kernel(
    const float* __restrict__ qkv, float* __restrict__ ao)
{
    __shared__ float Ks[64][65];
    __shared__ float Vs[64][65];
    int bh = blockIdx.y;
    int b = bh >> 3, h = bh & 7;
    int q0 = blockIdx.x * 64;
    int tid = threadIdx.x;
    int r = tid >> 2, cg = tid & 3;
    int lane = tid & 31;
    const float* base = qkv + (size_t)b * N * QKV_O;

    float q[16];
    {
        const float* qp = base + (size_t)(q0 + r) * QKV_O + h * DH + cg * 16;
        #pragma unroll
        for (int j = 0; j < 16; j++) q[j] = qp[j];
    }
    float mrow = -1e30f, l = 0.f;
    float acc[16];
    #pragma unroll
    for (int j = 0; j < 16; j++) acc[j] = 0.f;

    for (int kv0 = 0; kv0 < N; kv0 += 64) {
        #pragma unroll
        for (int u = 0; u < 16; u++) {
            int idx = tid + u * 256;
            int c = idx >> 6, k = idx & 63;
            const float* kvp = base + (size_t)(kv0 + c) * QKV_O + h * DH + k;
            Ks[c][k] = kvp[C];        // K at channel offset 512
            Vs[c][k] = kvp[2 * C];    // V at channel offset 1024
        }
        __syncthreads();

        // S[r][cg*16+j] = sum_k q[r][k] * K[c][k]; q[k] fetched via shfl from
        // the lane (same r, cg = k/16) that owns it.
        float s[16];
        #pragma unroll
        for (int j = 0; j < 16; j++) s[j] = 0.f;
        for (int kc = 0; kc < 4; kc++) {
            #pragma unroll
            for (int ki = 0; ki < 16; ki++) {
                float qk = __shfl_sync(0xffffffffu, q[ki], (lane & 28) | kc, 32);
                int k = kc * 16 + ki;
                #pragma unroll
                for (int j = 0; j < 16; j++)
                    s[j] = fmaf(qk, Ks[cg * 16 + j][k], s[j]);
            }
        }

        // online softmax (row stats reduced across the 4 cg lanes)
        float tmax = -1e30f;
        #pragma unroll
        for (int j = 0; j < 16; j++) { s[j] *= 0.125f; tmax = fmaxf(tmax, s[j]); }
        tmax = fmaxf(tmax, __shfl_xor_sync(0xffffffffu, tmax, 1));
        tmax = fmaxf(tmax, __shfl_xor_sync(0xffffffffu, tmax, 2));
        float mnew = fmaxf(mrow, tmax);
        float resc = __expf(mrow - mnew);
        float tsum = 0.f;
        #pragma unroll
        for (int j = 0; j < 16; j++) { s[j] = __expf(s[j] - mnew); tsum += s[j]; }
        tsum += __shfl_xor_sync(0xffffffffu, tsum, 1);
        tsum += __shfl_xor_sync(0xffffffffu, tsum, 2);
        l = l * resc + tsum;
        #pragma unroll
        for (int j = 0; j < 16; j++) acc[j] *= resc;
        mrow = mnew;

        // O[r][cg*16+jd] += sum_c P[r][c] * V[c][d]; rotate P across the 4
        // cg lanes so each thread sees all 64 columns.
        for (int st = 0; st < 4; st++) {
            int scg = cg ^ st;
            #pragma unroll
            for (int jc = 0; jc < 16; jc++) {
                float pv = __shfl_xor_sync(0xffffffffu, s[jc], st, 32);
                int c = scg * 16 + jc;
                #pragma unroll
                for (int jd = 0; jd < 16; jd++)
                    acc[jd] = fmaf(pv, Vs[c][cg * 16 + jd], acc[jd]);
            }
        }
        __syncthreads();
    }

    float invl = 1.f / l;
    float* op = ao + (size_t)(b * N + q0 + r) * C + h * DH + cg * 16;
    #pragma unroll
    for (int j = 0; j < 16; j++) op[j] = acc[j] * invl;
}

// ---------------------------------------------------------------------------

extern "C" void kernel_launch(void* const* d_in, const int* in_sizes, int n_in,
                              void* d_out, int out_size) {
    (void)in_sizes; (void)n_in; (void)out_size;
    const float* x    = (const float*)d_in[0];
    const float* Wqkv = (const float*)d_in[1];
    const float* Wprj = (const float*)d_in[2];
    float* out = (float*)d_out;

    float *pWq, *pWp, *pxn, *pqkv, *pao, *paon;
    cudaGetSymbolAddress((void**)&pWq,  g_Wqkv);
    cudaGetSymbolAddress((void**)&pWp,  g_Wprj);
    cudaGetSymbolAddress((void**)&pxn,  g_xnorm);
    cudaGetSymbolAddress((void**)&pqkv, g_qkv);
    cudaGetSymbolAddress((void**)&pao,  g_ao);
    cudaGetSymbolAddress((void**)&paon, g_aonorm);

    // 1. normalize + permute weights
    norm_w_kernel<<<QKV_W, 128>>>(Wqkv, pWq, QKV_O);
    norm_w_kernel<<<PRJ_W, 128>>>(Wprj, pWp, PRJ_O);

    // 2. per-token input norms
    row_norm_kernel<<<M, 128>>>(x, pxn);

    // 3. fused bcos QKV projection: (4096 x 512) @ (512 x 3072) -> maxout 1536
    bcos_gemm_kernel<<<dim3(QKV_W / 128, M / 128), 256>>>(x, pWq, pxn, pqkv, QKV_O);

    // 4. flash attention per (b,h)
    attn_kernel<<<dim3(N / 64, B * H), 256>>>(pqkv, pao);

    // 5. attention-output norms
    row_norm_kernel<<<M, 128>>>(pao, paon);

    // 6. fused bcos output projection -> d_out
    bcos_gemm_kernel<<<dim3(PRJ_W / 128, M / 128), 256>>>(pao, pWp, paon, out, PRJ_O);
}

// round 3
// speedup vs baseline: 3.9361x; 3.9361x over previous
#include <cuda_runtime.h>

namespace {
constexpr int B  = 2;
constexpr int N  = 2048;
constexpr int C  = 512;
constexpr int H  = 8;
constexpr int DH = 64;
constexpr int M  = B * N;          // 4096 tokens
constexpr int QKV_W = 3 * C * 2;   // 3072 weight rows
constexpr int QKV_O = 3 * C;       // 1536 fused outputs
constexpr int PRJ_W = C * 2;       // 1024 weight rows
constexpr int PRJ_O = C;           // 512 fused outputs
}

// Scratch (device globals — no allocation allowed)
__device__ float g_Wqkv[(size_t)QKV_W * C];      // normalized + pair-permuted
__device__ float g_Wprj[(size_t)PRJ_W * C];
__device__ float g_xnorm[M];
__device__ float g_qkv[(size_t)M * QKV_O];       // (b*n, [q|k|v])
__device__ float g_ao[(size_t)M * C];            // attention output
__device__ float g_aonorm[M];

// ---------------------------------------------------------------------------
// Normalize weight rows; permute so maxout partners (o, o+half) land at
// positions (g*32 + o%16) and (g*32 + o%16 + 16) with g = o/16.
// ---------------------------------------------------------------------------
__global__ void norm_w_kernel(const float* __restrict__ W,
                              float* __restrict__ dst, int half) {
    int r = blockIdx.x, t = threadIdx.x;
    const float* src = W + (size_t)r * C;
    float s = 0.f;
    for (int i = t; i < C; i += 128) { float v = src[i]; s += v * v; }
    #pragma unroll
    for (int o = 16; o; o >>= 1) s += __shfl_xor_sync(0xffffffffu, s, o);
    __shared__ float sm[4];
    if ((t & 31) == 0) sm[t >> 5] = s;
    __syncthreads();
    float inv = rsqrtf(sm[0] + sm[1] + sm[2] + sm[3]);
    int o = (r < half) ? r : r - half;
    int member = (r < half) ? 0 : 1;
    int dr = (o >> 4) * 32 + (o & 15) + member * 16;
    float* d = dst + (size_t)dr * C;
    for (int i = t; i < C; i += 128) d[i] = src[i] * inv;
}

__global__ void row_norm_kernel(const float* __restrict__ A,
                                float* __restrict__ out) {
    int r = blockIdx.x, t = threadIdx.x;
    const float* src = A + (size_t)r * C;
    float s = 0.f;
    for (int i = t; i < C; i += 128) { float v = src[i]; s += v * v; }
    #pragma unroll
    for (int o = 16; o; o >>= 1) s += __shfl_xor_sync(0xffffffffu, s, o);
    __shared__ float sm[4];
    if ((t & 31) == 0) sm[t >> 5] = s;
    __syncthreads();
    if (t == 0) out[r] = sqrtf(sm[0] + sm[1] + sm[2] + sm[3]);
}

// ---------------------------------------------------------------------------
// Fused Bcos GEMM, cp.async double-buffered. Row-major smem tiles [128][36].
// 128x128x32 tiles, 256 thr, 8x8 microtile, 2 blocks/SM.
// ---------------------------------------------------------------------------
__device__ __forceinline__ void cp_async16(void* s, const void* g) {
    unsigned sa = (unsigned)__cvta_generic_to_shared(s);
    asm volatile("cp.async.cg.shared.global [%0], [%1], 16;\n" :: "r"(sa), "l"(g));
}

__global__ __launch_bounds__(256, 2) void bcos_gemm_kernel(
    const float* __restrict__ A, const float* __restrict__ Wp,
    const float* __restrict__ norms, float* __restrict__ out, int nout)
{
    extern __shared__ float smem[];
    float* As = smem;                 // [2][128][36]
    float* Ws = smem + 2 * 128 * 36;  // [2][128][36]
    const int tid = threadIdx.x;
    const int tx = tid & 15, ty = tid >> 4;
    const int bm = blockIdx.y * 128;
    const int bc = blockIdx.x * 128;

    // loader: 1024 16B-chunks per matrix per tile; 4 per thread
    const int lrow = tid >> 1;            // base row pattern for u-loop
    (void)lrow;

    auto load_tile = [&](int k0, int buf) {
        float* as = As + buf * 128 * 36;
        float* ws = Ws + buf * 128 * 36;
        #pragma unroll
        for (int u = 0; u < 4; u++) {
            int ch = tid + u * 256;
            int row = ch >> 3, seg = ch & 7;
            cp_async16(as + row * 36 + seg * 4,
                       A + (size_t)(bm + row) * C + k0 + seg * 4);
            cp_async16(ws + row * 36 + seg * 4,
                       Wp + (size_t)(bc + row) * C + k0 + seg * 4);
        }
        asm volatile("cp.async.commit_group;\n");
    };

    float acc[8][8];
    #pragma unroll
    for (int i = 0; i < 8; i++)
        #pragma unroll
        for (int j = 0; j < 8; j++) acc[i][j] = 0.f;

    load_tile(0, 0);

    for (int t = 0; t < 16; t++) {
        if (t + 1 < 16) {
            load_tile((t + 1) * 32, (t + 1) & 1);
            asm volatile("cp.async.wait_group 1;\n");
        } else {
            asm volatile("cp.async.wait_group 0;\n");
        }
        __syncthreads();
        const float* as = As + (t & 1) * 128 * 36;
        const float* ws = Ws + (t & 1) * 128 * 36;
        #pragma unroll 8
        for (int kk = 0; kk < 32; kk++) {
            float a[8], w[8];
            #pragma unroll
            for (int i = 0; i < 8; i++) a[i] = as[(ty * 8 + i) * 36 + kk];
            #pragma unroll
            for (int j = 0; j < 8; j++) w[j] = ws[(tx + 16 * j) * 36 + kk];
            #pragma unroll
            for (int i = 0; i < 8; i++)
                #pragma unroll
                for (int j = 0; j < 8; j++)
                    acc[i][j] = fmaf(a[i], w[j], acc[i][j]);
        }
        __syncthreads();
    }

    const float sc = rsqrtf((float)C);
    #pragma unroll
    for (int i = 0; i < 8; i++) {
        int m = bm + ty * 8 + i;
        float inv = sc / norms[m];
        #pragma unroll
        for (int jp = 0; jp < 4; jp++) {
            float v = fmaxf(acc[i][2 * jp], acc[i][2 * jp + 1]);
            out[(size_t)m * nout + (bc >> 1) + jp * 16 + tx] = v * fabsf(v) * inv;
        }
    }
}

// ---------------------------------------------------------------------------
// Flash attention, fp32, register-tiled. Block = one (b,h) x 128-query tile.
// 256 threads: thread (tx = tid&15, ty = tid>>4) owns S/O tile rows
// ty*8..+7, cols tx*4..+3. Row stats reduced across the 16 tx lanes (shfl).
// smem: Qs[128][65] Ks[64][65] Vs[64][65] Ps[128][65]  (97.5 KB dynamic)
// ---------------------------------------------------------------------------
__global__ __launch_bounds__(256, 2) void attn_kernel(
    const float* __restrict__ qkv, float* __restrict__ ao)
{
    extern __shared__ float smem[];
    float* Qs = smem;                  // [128][65]
    float* Ks = Qs + 128 * 65;         // [64][65]
    float* Vs = Ks + 64 * 65;          // [64][65]
    float* Ps = Vs + 64 * 65;          // [128][65]

    const int bh = blockIdx.y;
    const int b = bh >> 3, h = bh & 7;
    const int q0 = blockIdx.x * 128;
    const int tid = threadIdx.x;
    const int tx = tid & 15, ty = tid >> 4;
    const float* base = qkv + (size_t)b * N * QKV_O;
    const int hoff = h * DH;

    // load Q tile (128 x 64), coalesced float4, scalar STS (pad-65 rows)
    #pragma unroll
    for (int u = 0; u < 8; u++) {
        int f4 = tid + u * 256;
        int r = f4 >> 4, k4 = f4 & 15;
        float4 v = *(const float4*)(base + (size_t)(q0 + r) * QKV_O + hoff + k4 * 4);
        float* d = Qs + r * 65 + k4 * 4;
        d[0] = v.x; d[1] = v.y; d[2] = v.z; d[3] = v.w;
    }

    float mrow[8], lrow[8], o[8][4];
    #pragma unroll
    for (int i = 0; i < 8; i++) {
        mrow[i] = -1e30f; lrow[i] = 0.f;
        #pragma unroll
        for (int j = 0; j < 4; j++) o[i][j] = 0.f;
    }

    for (int kv0 = 0; kv0 < N; kv0 += 64) {
        // load K/V tiles (64 x 64 each)
        #pragma unroll
        for (int u = 0; u < 4; u++) {
            int f4 = tid + u * 256;
            int c = f4 >> 4, k4 = f4 & 15;
            const float* gp = base + (size_t)(kv0 + c) * QKV_O + hoff + k4 * 4;
            float4 kk = *(const float4*)(gp + C);
            float4 vv = *(const float4*)(gp + 2 * C);
            float* kd = Ks + c * 65 + k4 * 4;
            kd[0] = kk.x; kd[1] = kk.y; kd[2] = kk.z; kd[3] = kk.w;
            float* vd = Vs + c * 65 + k4 * 4;
            vd[0] = vv.x; vd[1] = vv.y; vd[2] = vv.z; vd[3] = vv.w;
        }
        __syncthreads();

        // S = Q K^T  (8x4 per thread)
        float s[8][4];
        #pragma unroll
        for (int i = 0; i < 8; i++)
            #pragma unroll
            for (int j = 0; j < 4; j++) s[i][j] = 0.f;
        #pragma unroll 8
        for (int k = 0; k < 64; k++) {
            float kv[4];
            #pragma unroll
            for (int j = 0; j < 4; j++) kv[j] = Ks[(tx * 4 + j) * 65 + k];
            #pragma unroll
            for (int i = 0; i < 8; i++) {
                float qv = Qs[(ty * 8 + i) * 65 + k];
                #pragma unroll
                for (int j = 0; j < 4; j++)
                    s[i][j] = fmaf(qv, kv[j], s[i][j]);
            }
        }

        // online softmax per row (reduce over 16 tx lanes)
        #pragma unroll
        for (int i = 0; i < 8; i++) {
            float tm = -1e30f;
            #pragma unroll
            for (int j = 0; j < 4; j++) { s[i][j] *= 0.125f; tm = fmaxf(tm, s[i][j]); }
            tm = fmaxf(tm, __shfl_xor_sync(0xffffffffu, tm, 1));
            tm = fmaxf(tm, __shfl_xor_sync(0xffffffffu, tm, 2));
            tm = fmaxf(tm, __shfl_xor_sync(0xffffffffu, tm, 4));
            tm = fmaxf(tm, __shfl_xor_sync(0xffffffffu, tm, 8));
            float mn = fmaxf(mrow[i], tm);
            float rs = __expf(mrow[i] - mn);
            float ts = 0.f;
            #pragma unroll
            for (int j = 0; j < 4; j++) { s[i][j] = __expf(s[i][j] - mn); ts += s[i][j]; }
            ts += __shfl_xor_sync(0xffffffffu, ts, 1);
            ts += __shfl_xor_sync(0xffffffffu, ts, 2);
            ts += __shfl_xor_sync(0xffffffffu, ts, 4);
            ts += __shfl_xor_sync(0xffffffffu, ts, 8);
            lrow[i] = lrow[i] * rs + ts;
            mrow[i] = mn;
            #pragma unroll
            for (int j = 0; j < 4; j++) o[i][j] *= rs;
            float* pd = Ps + (ty * 8 + i) * 65 + tx * 4;
            pd[0] = s[i][0]; pd[1] = s[i][1]; pd[2] = s[i][2]; pd[3] = s[i][3];
        }
        __syncthreads();

        // O += P V  (8x4 per thread)
        #pragma unroll 8
        for (int c = 0; c < 64; c++) {
            float vv[4];
            #pragma unroll
            for (int j = 0; j < 4; j++) vv[j] = Vs[c * 65 + tx * 4 + j];
            #pragma unroll
            for (int i = 0; i < 8; i++) {
                float pv = Ps[(ty * 8 + i) * 65 + c];
                #pragma unroll
                for (int j = 0; j < 4; j++)
                    o[i][j] = fmaf(pv, vv[j], o[i][j]);
            }
        }
        __syncthreads();
    }

    #pragma unroll
    for (int i = 0; i < 8; i++) {
        float inv = 1.f / lrow[i];
        float* op = ao + (size_t)(b * N + q0 + ty * 8 + i) * C + hoff + tx * 4;
        op[0] = o[i][0] * inv; op[1] = o[i][1] * inv;
        op[2] = o[i][2] * inv; op[3] = o[i][3] * inv;
    }
}

// ---------------------------------------------------------------------------

extern "C" void kernel_launch(void* const* d_in, const int* in_sizes, int n_in,
                              void* d_out, int out_size) {
    (void)in_sizes; (void)n_in; (void)out_size;
    const float* x    = (const float*)d_in[0];
    const float* Wqkv = (const float*)d_in[1];
    const float* Wprj = (const float*)d_in[2];
    float* out = (float*)d_out;

    float *pWq, *pWp, *pxn, *pqkv, *pao, *paon;
    cudaGetSymbolAddress((void**)&pWq,  g_Wqkv);
    cudaGetSymbolAddress((void**)&pWp,  g_Wprj);
    cudaGetSymbolAddress((void**)&pxn,  g_xnorm);
    cudaGetSymbolAddress((void**)&pqkv, g_qkv);
    cudaGetSymbolAddress((void**)&pao,  g_ao);
    cudaGetSymbolAddress((void**)&paon, g_aonorm);

    const int gemm_smem = 4 * 128 * 36 * sizeof(float);   // 73728
    const int attn_smem = (128 + 64 + 64 + 128) * 65 * sizeof(float); // 99840
    cudaFuncSetAttribute(bcos_gemm_kernel,
                         cudaFuncAttributeMaxDynamicSharedMemorySize, gemm_smem);
    cudaFuncSetAttribute(attn_kernel,
                         cudaFuncAttributeMaxDynamicSharedMemorySize, attn_smem);

    // 1. normalize + permute weights
    norm_w_kernel<<<QKV_W, 128>>>(Wqkv, pWq, QKV_O);
    norm_w_kernel<<<PRJ_W, 128>>>(Wprj, pWp, PRJ_O);

    // 2. per-token input norms
    row_norm_kernel<<<M, 128>>>(x, pxn);

    // 3. fused bcos QKV projection
    bcos_gemm_kernel<<<dim3(QKV_W / 128, M / 128), 256, gemm_smem>>>(
        x, pWq, pxn, pqkv, QKV_O);

    // 4. flash attention per (b,h)
    attn_kernel<<<dim3(N / 128, B * H), 256, attn_smem>>>(pqkv, pao);

    // 5. attention-output norms
    row_norm_kernel<<<M, 128>>>(pao, paon);

    // 6. fused bcos output projection -> d_out
    bcos_gemm_kernel<<<dim3(PRJ_W / 128, M / 128), 256, gemm_smem>>>(
        pao, pWp, paon, out, PRJ_O);
}

// round 5
// speedup vs baseline: 5.8475x; 1.4856x over previous
#include <cuda_runtime.h>
#include <cuda_bf16.h>
#include <cstdint>

namespace {
constexpr int B  = 2;
constexpr int N  = 2048;
constexpr int C  = 512;
constexpr int H  = 8;
constexpr int DH = 64;
constexpr int M  = B * N;          // 4096 tokens
constexpr int QKV_W = 3 * C * 2;   // 3072 weight rows
constexpr int QKV_O = 3 * C;       // 1536 fused outputs
constexpr int PRJ_W = C * 2;       // 1024 weight rows
constexpr int PRJ_O = C;           // 512 fused outputs

constexpr int BM = 128;            // M tile
constexpr int BN = 128;            // weight-row tile
constexpr int BK = 64;             // K tile (bf16) = 128 bytes/row
constexpr int NT = 24;             // 3 split phases * (512/64)
constexpr int TILE_BYTES = BM * 128;            // 16 KB per matrix
constexpr int BUF_BYTES  = 2 * TILE_BYTES;      // A+B per stage
constexpr int GEMM_SMEM  = 2 * BUF_BYTES + 128; // double buffer + align
}

// Scratch (device globals — no allocation allowed)
__device__ __nv_bfloat16 g_xh[(size_t)M * C];
__device__ __nv_bfloat16 g_xl[(size_t)M * C];
__device__ __nv_bfloat16 g_Wqh[(size_t)QKV_W * C];
__device__ __nv_bfloat16 g_Wql[(size_t)QKV_W * C];
__device__ __nv_bfloat16 g_Wph[(size_t)PRJ_W * C];
__device__ __nv_bfloat16 g_Wpl[(size_t)PRJ_W * C];
__device__ __nv_bfloat16 g_aoh[(size_t)M * C];
__device__ __nv_bfloat16 g_aol[(size_t)M * C];
__device__ float g_xnorm[M];
__device__ float g_aonorm[M];
__device__ float g_qkv[(size_t)M * QKV_O];
__device__ float g_ao[(size_t)M * C];

// ---------------------------------------------------------------------------
// PTX helpers (all baseline compute_103-safe: cp.async sm_80, ldmatrix sm_75,
// mma.sync bf16 sm_80)
// ---------------------------------------------------------------------------
__device__ __forceinline__ uint32_t smem_u32(const void* p) {
    return (uint32_t)__cvta_generic_to_shared(p);
}
__device__ __forceinline__ void cp16(uint32_t s, const void* g) {
    asm volatile("cp.async.cg.shared.global [%0], [%1], 16;\n" :: "r"(s), "l"(g));
}
__device__ __forceinline__ uint32_t sw128(uint32_t off) {
    return off ^ ((off >> 3) & 0x70);
}
__device__ __forceinline__ void ldm_x4(uint32_t* r, uint32_t addr) {
    asm volatile("ldmatrix.sync.aligned.m8n8.x4.shared.b16 {%0,%1,%2,%3}, [%4];"
                 : "=r"(r[0]), "=r"(r[1]), "=r"(r[2]), "=r"(r[3]) : "r"(addr));
}
__device__ __forceinline__ void mma16816(float* c, const uint32_t* a,
                                         const uint32_t* b) {
    asm volatile(
        "mma.sync.aligned.m16n8k16.row.col.f32.bf16.bf16.f32 "
        "{%0,%1,%2,%3}, {%4,%5,%6,%7}, {%8,%9}, {%0,%1,%2,%3};"
        : "+f"(c[0]), "+f"(c[1]), "+f"(c[2]), "+f"(c[3])
        : "r"(a[0]), "r"(a[1]), "r"(a[2]), "r"(a[3]), "r"(b[0]), "r"(b[1]));
}

// ---------------------------------------------------------------------------
// prep: per-row L2 norm + bf16 hi/lo split (activations)
// ---------------------------------------------------------------------------
__global__ void prep_act_kernel(const float* __restrict__ A,
                                __nv_bfloat16* __restrict__ Ah,
                                __nv_bfloat16* __restrict__ Al,
                                float* __restrict__ norms) {
    int r = blockIdx.x, t = threadIdx.x;
    float4 v = ((const float4*)(A + (size_t)r * C))[t];
    float s = v.x * v.x + v.y * v.y + v.z * v.z + v.w * v.w;
    #pragma unroll
    for (int o = 16; o; o >>= 1) s += __shfl_xor_sync(0xffffffffu, s, o);
    __shared__ float sm[4];
    if ((t & 31) == 0) sm[t >> 5] = s;
    __syncthreads();
    if (t == 0) norms[r] = sqrtf(sm[0] + sm[1] + sm[2] + sm[3]);
    float va[4] = {v.x, v.y, v.z, v.w};
    #pragma unroll
    for (int j = 0; j < 4; j++) {
        __nv_bfloat16 h = __float2bfloat16(va[j]);
        __nv_bfloat16 l = __float2bfloat16(va[j] - __bfloat162float(h));
        Ah[(size_t)r * C + t * 4 + j] = h;
        Al[(size_t)r * C + t * 4 + j] = l;
    }
}

// ---------------------------------------------------------------------------
// prep: normalize weight rows, permute maxout partners ADJACENT
// (row o -> 2o, row o+half -> 2o+1), split into bf16 hi/lo.
// ---------------------------------------------------------------------------
__global__ void prep_w_kernel(const float* __restrict__ W,
                              __nv_bfloat16* __restrict__ Dh,
                              __nv_bfloat16* __restrict__ Dl, int half) {
    int r = blockIdx.x, t = threadIdx.x;
    float4 v = ((const float4*)(W + (size_t)r * C))[t];
    float s = v.x * v.x + v.y * v.y + v.z * v.z + v.w * v.w;
    #pragma unroll
    for (int o = 16; o; o >>= 1) s += __shfl_xor_sync(0xffffffffu, s, o);
    __shared__ float sm[4];
    if ((t & 31) == 0) sm[t >> 5] = s;
    __syncthreads();
    float inv = rsqrtf(sm[0] + sm[1] + sm[2] + sm[3]);
    int dr = (r < half) ? 2 * r : 2 * (r - half) + 1;
    float va[4] = {v.x, v.y, v.z, v.w};
    #pragma unroll
    for (int j = 0; j < 4; j++) {
        float w = va[j] * inv;
        __nv_bfloat16 h = __float2bfloat16(w);
        __nv_bfloat16 l = __float2bfloat16(w - __bfloat162float(h));
        Dh[(size_t)dr * C + t * 4 + j] = h;
        Dl[(size_t)dr * C + t * 4 + j] = l;
    }
}

// ---------------------------------------------------------------------------
// mma.sync bcos GEMM (bf16x3): out[m][o] = f(max over adjacent col pair)
// 128x128x64 tiles, 8 warps (2M x 4N), warp tile 64x32, double-buffered.
// ---------------------------------------------------------------------------
__global__ __launch_bounds__(256, 2) void tc_gemm_kernel(
    const __nv_bfloat16* __restrict__ Ah, const __nv_bfloat16* __restrict__ Al,
    const __nv_bfloat16* __restrict__ Wh, const __nv_bfloat16* __restrict__ Wl,
    const float* __restrict__ norms, float* __restrict__ out, int nout)
{
    extern __shared__ char smem[];
    const uint32_t tiles = (smem_u32(smem) + 127) & ~127u;
    const int tid = threadIdx.x;
    const int lane = tid & 31;
    const int warp = tid >> 5;
    const int wm = warp >> 2;      // 0..1
    const int wn = warp & 3;       // 0..3
    const int bm = blockIdx.y * BM;
    const int bc = blockIdx.x * BN;

    auto load_tile = [&](int t) {
        int phase = t >> 3;
        int k0 = (t & 7) * BK;
        const __nv_bfloat16* As = (phase == 2) ? Al : Ah;
        const __nv_bfloat16* Ws = (phase == 1) ? Wl : Wh;
        uint32_t ab = tiles + (t & 1) * BUF_BYTES;
        uint32_t bb = ab + TILE_BYTES;
        #pragma unroll
        for (int u = 0; u < 4; u++) {
            int c = tid + u * 256;
            int row = c >> 3, seg = c & 7;
            uint32_t sw = sw128(row * 128 + seg * 16);
            cp16(ab + sw, As + (size_t)(bm + row) * C + k0 + seg * 8);
            cp16(bb + sw, Ws + (size_t)(bc + row) * C + k0 + seg * 8);
        }
        asm volatile("cp.async.commit_group;\n");
    };

    float acc[4][4][4];
    #pragma unroll
    for (int i = 0; i < 4; i++)
        #pragma unroll
        for (int j = 0; j < 4; j++)
            #pragma unroll
            for (int q = 0; q < 4; q++) acc[i][j][q] = 0.f;

    load_tile(0);

    for (int t = 0; t < NT; t++) {
        if (t + 1 < NT) {
            load_tile(t + 1);
            asm volatile("cp.async.wait_group 1;\n" ::: "memory");
        } else {
            asm volatile("cp.async.wait_group 0;\n" ::: "memory");
        }
        __syncthreads();
        uint32_t ab = tiles + (t & 1) * BUF_BYTES;
        uint32_t bb = ab + TILE_BYTES;

        #pragma unroll
        for (int ks = 0; ks < 4; ks++) {
            uint32_t afrag[4][4], bfrag[2][4];
            #pragma unroll
            for (int mt = 0; mt < 4; mt++) {
                int row = wm * 64 + mt * 16 + (lane & 15);
                int seg = ks * 2 + (lane >> 4);
                ldm_x4(afrag[mt], ab + sw128(row * 128 + seg * 16));
            }
            #pragma unroll
            for (int p = 0; p < 2; p++) {
                int row = wn * 32 + p * 16 + (lane & 7) + ((lane >> 4) << 3);
                int seg = ks * 2 + ((lane >> 3) & 1);
                ldm_x4(bfrag[p], bb + sw128(row * 128 + seg * 16));
            }
            #pragma unroll
            for (int mt = 0; mt < 4; mt++)
                #pragma unroll
                for (int nt = 0; nt < 4; nt++)
                    mma16816(acc[mt][nt], afrag[mt], &bfrag[nt >> 1][(nt & 1) * 2]);
        }
        __syncthreads();
    }

    // Epilogue: c0/c1 and c2/c3 are adjacent weight cols = maxout pairs.
    const float sc = rsqrtf((float)C);
    const int g = lane >> 2, tig = lane & 3;
    #pragma unroll
    for (int mt = 0; mt < 4; mt++) {
        int m0 = bm + wm * 64 + mt * 16;
        int r0 = m0 + g, r1 = m0 + g + 8;
        float inv0 = sc / norms[r0];
        float inv1 = sc / norms[r1];
        #pragma unroll
        for (int nt = 0; nt < 4; nt++) {
            int col = (bc >> 1) + wn * 16 + nt * 4 + tig;
            float v0 = fmaxf(acc[mt][nt][0], acc[mt][nt][1]);
            out[(size_t)r0 * nout + col] = v0 * fabsf(v0) * inv0;
            float v1 = fmaxf(acc[mt][nt][2], acc[mt][nt][3]);
            out[(size_t)r1 * nout + col] = v1 * fabsf(v1) * inv1;
        }
    }
}

// ---------------------------------------------------------------------------
// Flash attention, fp32, register-tiled (unchanged from R3 — passed).
// ---------------------------------------------------------------------------
__global__ __launch_bounds__(256, 2) void attn_kernel(
    const float* __restrict__ qkv, float* __restrict__ ao)
{
    extern __shared__ float fsm[];
    float* Qs = fsm;                   // [128][65]
    float* Ks = Qs + 128 * 65;         // [64][65]
    float* Vs = Ks + 64 * 65;          // [64][65]
    float* Ps = Vs + 64 * 65;          // [128][65]

    const int bh = blockIdx.y;
    const int b = bh >> 3, h = bh & 7;
    const int q0 = blockIdx.x * 128;
    const int tid = threadIdx.x;
    const int tx = tid & 15, ty = tid >> 4;
    const float* base = qkv + (size_t)b * N * QKV_O;
    const int hoff = h * DH;

    #pragma unroll
    for (int u = 0; u < 8; u++) {
        int f4 = tid + u * 256;
        int r = f4 >> 4, k4 = f4 & 15;
        float4 v = *(const float4*)(base + (size_t)(q0 + r) * QKV_O + hoff + k4 * 4);
        float* d = Qs + r * 65 + k4 * 4;
        d[0] = v.x; d[1] = v.y; d[2] = v.z; d[3] = v.w;
    }

    float mrow[8], lrow[8], o[8][4];
    #pragma unroll
    for (int i = 0; i < 8; i++) {
        mrow[i] = -1e30f; lrow[i] = 0.f;
        #pragma unroll
        for (int j = 0; j < 4; j++) o[i][j] = 0.f;
    }

    for (int kv0 = 0; kv0 < N; kv0 += 64) {
        #pragma unroll
        for (int u = 0; u < 4; u++) {
            int f4 = tid + u * 256;
            int c = f4 >> 4, k4 = f4 & 15;
            const float* gp = base + (size_t)(kv0 + c) * QKV_O + hoff + k4 * 4;
            float4 kk = *(const float4*)(gp + C);
            float4 vv = *(const float4*)(gp + 2 * C);
            float* kd = Ks + c * 65 + k4 * 4;
            kd[0] = kk.x; kd[1] = kk.y; kd[2] = kk.z; kd[3] = kk.w;
            float* vd = Vs + c * 65 + k4 * 4;
            vd[0] = vv.x; vd[1] = vv.y; vd[2] = vv.z; vd[3] = vv.w;
        }
        __syncthreads();

        float s[8][4];
        #pragma unroll
        for (int i = 0; i < 8; i++)
            #pragma unroll
            for (int j = 0; j < 4; j++) s[i][j] = 0.f;
        #pragma unroll 8
        for (int k = 0; k < 64; k++) {
            float kv[4];
            #pragma unroll
            for (int j = 0; j < 4; j++) kv[j] = Ks[(tx * 4 + j) * 65 + k];
            #pragma unroll
            for (int i = 0; i < 8; i++) {
                float qv = Qs[(ty * 8 + i) * 65 + k];
                #pragma unroll
                for (int j = 0; j < 4; j++)
                    s[i][j] = fmaf(qv, kv[j], s[i][j]);
            }
        }

        #pragma unroll
        for (int i = 0; i < 8; i++) {
            float tm = -1e30f;
            #pragma unroll
            for (int j = 0; j < 4; j++) { s[i][j] *= 0.125f; tm = fmaxf(tm, s[i][j]); }
            tm = fmaxf(tm, __shfl_xor_sync(0xffffffffu, tm, 1));
            tm = fmaxf(tm, __shfl_xor_sync(0xffffffffu, tm, 2));
            tm = fmaxf(tm, __shfl_xor_sync(0xffffffffu, tm, 4));
            tm = fmaxf(tm, __shfl_xor_sync(0xffffffffu, tm, 8));
            float mn = fmaxf(mrow[i], tm);
            float rs = __expf(mrow[i] - mn);
            float ts = 0.f;
            #pragma unroll
            for (int j = 0; j < 4; j++) { s[i][j] = __expf(s[i][j] - mn); ts += s[i][j]; }
            ts += __shfl_xor_sync(0xffffffffu, ts, 1);
            ts += __shfl_xor_sync(0xffffffffu, ts, 2);
            ts += __shfl_xor_sync(0xffffffffu, ts, 4);
            ts += __shfl_xor_sync(0xffffffffu, ts, 8);
            lrow[i] = lrow[i] * rs + ts;
            mrow[i] = mn;
            #pragma unroll
            for (int j = 0; j < 4; j++) o[i][j] *= rs;
            float* pd = Ps + (ty * 8 + i) * 65 + tx * 4;
            pd[0] = s[i][0]; pd[1] = s[i][1]; pd[2] = s[i][2]; pd[3] = s[i][3];
        }
        __syncthreads();

        #pragma unroll 8
        for (int c = 0; c < 64; c++) {
            float vv[4];
            #pragma unroll
            for (int j = 0; j < 4; j++) vv[j] = Vs[c * 65 + tx * 4 + j];
            #pragma unroll
            for (int i = 0; i < 8; i++) {
                float pv = Ps[(ty * 8 + i) * 65 + c];
                #pragma unroll
                for (int j = 0; j < 4; j++)
                    o[i][j] = fmaf(pv, vv[j], o[i][j]);
            }
        }
        __syncthreads();
    }

    #pragma unroll
    for (int i = 0; i < 8; i++) {
        float inv = 1.f / lrow[i];
        float* op = ao + (size_t)(b * N + q0 + ty * 8 + i) * C + hoff + tx * 4;
        op[0] = o[i][0] * inv; op[1] = o[i][1] * inv;
        op[2] = o[i][2] * inv; op[3] = o[i][3] * inv;
    }
}

// ---------------------------------------------------------------------------

extern "C" void kernel_launch(void* const* d_in, const int* in_sizes, int n_in,
                              void* d_out, int out_size) {
    (void)in_sizes; (void)n_in; (void)out_size;
    const float* x    = (const float*)d_in[0];
    const float* Wqkv = (const float*)d_in[1];
    const float* Wprj = (const float*)d_in[2];
    float* out = (float*)d_out;

    __nv_bfloat16 *pxh, *pxl, *pWqh, *pWql, *pWph, *pWpl, *paoh, *paol;
    float *pxn, *paon, *pqkv, *pao;
    cudaGetSymbolAddress((void**)&pxh,  g_xh);
    cudaGetSymbolAddress((void**)&pxl,  g_xl);
    cudaGetSymbolAddress((void**)&pWqh, g_Wqh);
    cudaGetSymbolAddress((void**)&pWql, g_Wql);
    cudaGetSymbolAddress((void**)&pWph, g_Wph);
    cudaGetSymbolAddress((void**)&pWpl, g_Wpl);
    cudaGetSymbolAddress((void**)&paoh, g_aoh);
    cudaGetSymbolAddress((void**)&paol, g_aol);
    cudaGetSymbolAddress((void**)&pxn,  g_xnorm);
    cudaGetSymbolAddress((void**)&paon, g_aonorm);
    cudaGetSymbolAddress((void**)&pqkv, g_qkv);
    cudaGetSymbolAddress((void**)&pao,  g_ao);

    const int attn_smem = (128 + 64 + 64 + 128) * 65 * sizeof(float); // 99840
    cudaFuncSetAttribute(tc_gemm_kernel,
                         cudaFuncAttributeMaxDynamicSharedMemorySize, GEMM_SMEM);
    cudaFuncSetAttribute(attn_kernel,
                         cudaFuncAttributeMaxDynamicSharedMemorySize, attn_smem);

    // 1. prep
    prep_w_kernel<<<QKV_W, 128>>>(Wqkv, pWqh, pWql, QKV_O);
    prep_w_kernel<<<PRJ_W, 128>>>(Wprj, pWph, pWpl, PRJ_O);
    prep_act_kernel<<<M, 128>>>(x, pxh, pxl, pxn);

    // 2. bcos QKV projection (mma.sync bf16x3)
    tc_gemm_kernel<<<dim3(QKV_W / BN, M / BM), 256, GEMM_SMEM>>>(
        pxh, pxl, pWqh, pWql, pxn, pqkv, QKV_O);

    // 3. flash attention (fp32)
    attn_kernel<<<dim3(N / 128, B * H), 256, attn_smem>>>(pqkv, pao);

    // 4. prep attention output
    prep_act_kernel<<<M, 128>>>(pao, paoh, paol, paon);

    // 5. bcos output projection -> d_out
    tc_gemm_kernel<<<dim3(PRJ_W / BN, M / BM), 256, GEMM_SMEM>>>(
        paoh, paol, pWph, pWpl, paon, out, PRJ_O);
}

// round 6
// speedup vs baseline: 11.7257x; 2.0052x over previous
#include <cuda_runtime.h>
#include <cuda_bf16.h>
#include <cstdint>

namespace {
constexpr int B  = 2;
constexpr int N  = 2048;
constexpr int C  = 512;
constexpr int H  = 8;
constexpr int DH = 64;
constexpr int M  = B * N;          // 4096 tokens
constexpr int QKV_W = 3 * C * 2;   // 3072 weight rows
constexpr int PRJ_W = C * 2;       // 1024 weight rows
constexpr int PRJ_O = C;           // 512 fused outputs

constexpr int BM = 128;
constexpr int BN = 128;
constexpr int BK = 64;             // K tile (bf16) = 128 bytes/row
constexpr int NT = 24;             // 3 split phases * (512/64)
constexpr int TILE_BYTES = BM * 128;
constexpr int BUF_BYTES  = 2 * TILE_BYTES;
constexpr int GEMM_SMEM  = 2 * BUF_BYTES + 128;

constexpr int ATTN_SMEM = 2 * 16384 + 2 * 32768;  // Qh/Ql + 2 KV stages = 96 KB
}

// Scratch (device globals — no allocation allowed)
__device__ __nv_bfloat16 g_xh[(size_t)M * C];
__device__ __nv_bfloat16 g_xl[(size_t)M * C];
__device__ __nv_bfloat16 g_Wqh[(size_t)QKV_W * C];
__device__ __nv_bfloat16 g_Wql[(size_t)QKV_W * C];
__device__ __nv_bfloat16 g_Wph[(size_t)PRJ_W * C];
__device__ __nv_bfloat16 g_Wpl[(size_t)PRJ_W * C];
__device__ __nv_bfloat16 g_aoh[(size_t)M * C];
__device__ __nv_bfloat16 g_aol[(size_t)M * C];
// attention-ready qkv, head-major: [bh][n][64], hi/lo bf16
__device__ __nv_bfloat16 g_qh[(size_t)B * H * N * DH];
__device__ __nv_bfloat16 g_ql[(size_t)B * H * N * DH];
__device__ __nv_bfloat16 g_kh[(size_t)B * H * N * DH];
__device__ __nv_bfloat16 g_kl[(size_t)B * H * N * DH];
__device__ __nv_bfloat16 g_vh[(size_t)B * H * N * DH];
__device__ __nv_bfloat16 g_vl[(size_t)B * H * N * DH];
__device__ float g_xnorm[M];
__device__ float g_aonorm[M];
__device__ float g_ao[(size_t)M * C];

// ---------------------------------------------------------------------------
// PTX helpers (compute_103-safe: cp.async, ldmatrix, mma.sync bf16)
// ---------------------------------------------------------------------------
__device__ __forceinline__ uint32_t smem_u32(const void* p) {
    return (uint32_t)__cvta_generic_to_shared(p);
}
__device__ __forceinline__ void cp16(uint32_t s, const void* g) {
    asm volatile("cp.async.cg.shared.global [%0], [%1], 16;\n" :: "r"(s), "l"(g));
}
__device__ __forceinline__ uint32_t sw128(uint32_t off) {
    return off ^ ((off >> 3) & 0x70);
}
__device__ __forceinline__ void ldm_x4(uint32_t* r, uint32_t addr) {
    asm volatile("ldmatrix.sync.aligned.m8n8.x4.shared.b16 {%0,%1,%2,%3}, [%4];"
                 : "=r"(r[0]), "=r"(r[1]), "=r"(r[2]), "=r"(r[3]) : "r"(addr));
}
__device__ __forceinline__ void ldm_x4_t(uint32_t* r, uint32_t addr) {
    asm volatile("ldmatrix.sync.aligned.m8n8.x4.trans.shared.b16 {%0,%1,%2,%3}, [%4];"
                 : "=r"(r[0]), "=r"(r[1]), "=r"(r[2]), "=r"(r[3]) : "r"(addr));
}
__device__ __forceinline__ void mma16816(float* c, const uint32_t* a,
                                         const uint32_t* b) {
    asm volatile(
        "mma.sync.aligned.m16n8k16.row.col.f32.bf16.bf16.f32 "
        "{%0,%1,%2,%3}, {%4,%5,%6,%7}, {%8,%9}, {%0,%1,%2,%3};"
        : "+f"(c[0]), "+f"(c[1]), "+f"(c[2]), "+f"(c[3])
        : "r"(a[0]), "r"(a[1]), "r"(a[2]), "r"(a[3]), "r"(b[0]), "r"(b[1]));
}
__device__ __forceinline__ uint32_t packbf(float lo, float hi) {
    __nv_bfloat162 t = __floats2bfloat162_rn(lo, hi);
    return *(uint32_t*)&t;
}
__device__ __forceinline__ void split_pack(float lo, float hi,
                                           uint32_t& h, uint32_t& l) {
    h = packbf(lo, hi);
    __nv_bfloat162 hv = *(__nv_bfloat162*)&h;
    l = packbf(lo - __bfloat162float(hv.x), hi - __bfloat162float(hv.y));
}

// ---------------------------------------------------------------------------
// prep: per-row L2 norm + bf16 hi/lo split (activations)
// ---------------------------------------------------------------------------
__global__ void prep_act_kernel(const float* __restrict__ A,
                                __nv_bfloat16* __restrict__ Ah,
                                __nv_bfloat16* __restrict__ Al,
                                float* __restrict__ norms) {
    int r = blockIdx.x, t = threadIdx.x;
    float4 v = ((const float4*)(A + (size_t)r * C))[t];
    float s = v.x * v.x + v.y * v.y + v.z * v.z + v.w * v.w;
    #pragma unroll
    for (int o = 16; o; o >>= 1) s += __shfl_xor_sync(0xffffffffu, s, o);
    __shared__ float sm[4];
    if ((t & 31) == 0) sm[t >> 5] = s;
    __syncthreads();
    if (t == 0) norms[r] = sqrtf(sm[0] + sm[1] + sm[2] + sm[3]);
    float va[4] = {v.x, v.y, v.z, v.w};
    #pragma unroll
    for (int j = 0; j < 4; j++) {
        __nv_bfloat16 h = __float2bfloat16(va[j]);
        __nv_bfloat16 l = __float2bfloat16(va[j] - __bfloat162float(h));
        Ah[(size_t)r * C + t * 4 + j] = h;
        Al[(size_t)r * C + t * 4 + j] = l;
    }
}

// prep: normalize weight rows, maxout partners ADJACENT (o->2o, o+half->2o+1)
__global__ void prep_w_kernel(const float* __restrict__ W,
                              __nv_bfloat16* __restrict__ Dh,
                              __nv_bfloat16* __restrict__ Dl, int half) {
    int r = blockIdx.x, t = threadIdx.x;
    float4 v = ((const float4*)(W + (size_t)r * C))[t];
    float s = v.x * v.x + v.y * v.y + v.z * v.z + v.w * v.w;
    #pragma unroll
    for (int o = 16; o; o >>= 1) s += __shfl_xor_sync(0xffffffffu, s, o);
    __shared__ float sm[4];
    if ((t & 31) == 0) sm[t >> 5] = s;
    __syncthreads();
    float inv = rsqrtf(sm[0] + sm[1] + sm[2] + sm[3]);
    int dr = (r < half) ? 2 * r : 2 * (r - half) + 1;
    float va[4] = {v.x, v.y, v.z, v.w};
    #pragma unroll
    for (int j = 0; j < 4; j++) {
        float w = va[j] * inv;
        __nv_bfloat16 h = __float2bfloat16(w);
        __nv_bfloat16 l = __float2bfloat16(w - __bfloat162float(h));
        Dh[(size_t)dr * C + t * 4 + j] = h;
        Dl[(size_t)dr * C + t * 4 + j] = l;
    }
}

// ---------------------------------------------------------------------------
// mma.sync bcos GEMM (bf16x3). MODE 0: fp32 out (proj). MODE 1: bf16 hi/lo
// split scatter to head-major q/k/v buffers (q scaled by 0.125).
// ---------------------------------------------------------------------------
template <int MODE>
__global__ __launch_bounds__(256, 2) void tc_gemm_kernel(
    const __nv_bfloat16* __restrict__ Ah, const __nv_bfloat16* __restrict__ Al,
    const __nv_bfloat16* __restrict__ Wh, const __nv_bfloat16* __restrict__ Wl,
    const float* __restrict__ norms, float* __restrict__ out, int nout,
    __nv_bfloat16* __restrict__ qh, __nv_bfloat16* __restrict__ ql,
    __nv_bfloat16* __restrict__ kh, __nv_bfloat16* __restrict__ kl,
    __nv_bfloat16* __restrict__ vh, __nv_bfloat16* __restrict__ vl)
{
    extern __shared__ char smem[];
    const uint32_t tiles = (smem_u32(smem) + 127) & ~127u;
    const int tid = threadIdx.x;
    const int lane = tid & 31;
    const int warp = tid >> 5;
    const int wm = warp >> 2;
    const int wn = warp & 3;
    const int bm = blockIdx.y * BM;
    const int bc = blockIdx.x * BN;

    auto load_tile = [&](int t) {
        int phase = t >> 3;
        int k0 = (t & 7) * BK;
        const __nv_bfloat16* As = (phase == 2) ? Al : Ah;
        const __nv_bfloat16* Ws = (phase == 1) ? Wl : Wh;
        uint32_t ab = tiles + (t & 1) * BUF_BYTES;
        uint32_t bb = ab + TILE_BYTES;
        #pragma unroll
        for (int u = 0; u < 4; u++) {
            int c = tid + u * 256;
            int row = c >> 3, seg = c & 7;
            uint32_t sw = sw128(row * 128 + seg * 16);
            cp16(ab + sw, As + (size_t)(bm + row) * C + k0 + seg * 8);
            cp16(bb + sw, Ws + (size_t)(bc + row) * C + k0 + seg * 8);
        }
        asm volatile("cp.async.commit_group;\n");
    };

    float acc[4][4][4];
    #pragma unroll
    for (int i = 0; i < 4; i++)
        #pragma unroll
        for (int j = 0; j < 4; j++)
            #pragma unroll
            for (int q = 0; q < 4; q++) acc[i][j][q] = 0.f;

    load_tile(0);

    for (int t = 0; t < NT; t++) {
        if (t + 1 < NT) {
            load_tile(t + 1);
            asm volatile("cp.async.wait_group 1;\n" ::: "memory");
        } else {
            asm volatile("cp.async.wait_group 0;\n" ::: "memory");
        }
        __syncthreads();
        uint32_t ab = tiles + (t & 1) * BUF_BYTES;
        uint32_t bb = ab + TILE_BYTES;

        #pragma unroll
        for (int ks = 0; ks < 4; ks++) {
            uint32_t afrag[4][4], bfrag[2][4];
            #pragma unroll
            for (int mt = 0; mt < 4; mt++) {
                int row = wm * 64 + mt * 16 + (lane & 15);
                int seg = ks * 2 + (lane >> 4);
                ldm_x4(afrag[mt], ab + sw128(row * 128 + seg * 16));
            }
            #pragma unroll
            for (int p = 0; p < 2; p++) {
                int row = wn * 32 + p * 16 + (lane & 7) + ((lane >> 4) << 3);
                int seg = ks * 2 + ((lane >> 3) & 1);
                ldm_x4(bfrag[p], bb + sw128(row * 128 + seg * 16));
            }
            #pragma unroll
            for (int mt = 0; mt < 4; mt++)
                #pragma unroll
                for (int nt = 0; nt < 4; nt++)
                    mma16816(acc[mt][nt], afrag[mt], &bfrag[nt >> 1][(nt & 1) * 2]);
        }
        __syncthreads();
    }

    const float sc = rsqrtf((float)C);
    const int g = lane >> 2, tig = lane & 3;

    // MODE 1: block-uniform destination (64-col span within one section/head)
    __nv_bfloat16 *dsth = nullptr, *dstl = nullptr;
    float qscale = 1.f;
    int hh = 0;
    if (MODE == 1) {
        int colbase = bc >> 1;
        int sect = colbase >> 9;
        hh = (colbase & 511) >> 6;
        if (sect == 0)      { dsth = qh; dstl = ql; qscale = 0.125f; }
        else if (sect == 1) { dsth = kh; dstl = kl; }
        else                { dsth = vh; dstl = vl; }
    }

    #pragma unroll
    for (int mt = 0; mt < 4; mt++) {
        int m0 = bm + wm * 64 + mt * 16;
        int r0 = m0 + g, r1 = m0 + g + 8;
        float inv0 = sc / norms[r0];
        float inv1 = sc / norms[r1];
        #pragma unroll
        for (int nt = 0; nt < 4; nt++) {
            float v0 = fmaxf(acc[mt][nt][0], acc[mt][nt][1]);
            v0 = v0 * fabsf(v0) * inv0;
            float v1 = fmaxf(acc[mt][nt][2], acc[mt][nt][3]);
            v1 = v1 * fabsf(v1) * inv1;
            if (MODE == 0) {
                int col = (bc >> 1) + wn * 16 + nt * 4 + tig;
                out[(size_t)r0 * nout + col] = v0;
                out[(size_t)r1 * nout + col] = v1;
            } else {
                int d = wn * 16 + nt * 4 + tig;
                v0 *= qscale; v1 *= qscale;
                __nv_bfloat16 h0 = __float2bfloat16(v0);
                __nv_bfloat16 h1 = __float2bfloat16(v1);
                size_t i0 = ((size_t)(((r0 >> 11) << 3) + hh) * N + (r0 & 2047)) * DH + d;
                size_t i1 = ((size_t)(((r1 >> 11) << 3) + hh) * N + (r1 & 2047)) * DH + d;
                dsth[i0] = h0; dstl[i0] = __float2bfloat16(v0 - __bfloat162float(h0));
                dsth[i1] = h1; dstl[i1] = __float2bfloat16(v1 - __bfloat162float(h1));
            }
        }
    }
}

// ---------------------------------------------------------------------------
// Flash attention, mma.sync bf16 split. Block = 128 q-rows of one (b,h).
// 8 warps, warp w owns rows w*16..+15 (m16 x n64 S tile) -> warp-local softmax.
// QK^T = QhKh + QhKl + QlKh; PV = PhVh + PlVh + PhVl (P split in registers).
// ---------------------------------------------------------------------------
__global__ __launch_bounds__(256, 2) void attn_mma_kernel(
    const __nv_bfloat16* __restrict__ qh, const __nv_bfloat16* __restrict__ ql,
    const __nv_bfloat16* __restrict__ kh, const __nv_bfloat16* __restrict__ kl,
    const __nv_bfloat16* __restrict__ vh, const __nv_bfloat16* __restrict__ vl,
    float* __restrict__ ao)
{
    extern __shared__ char smem[];
    const uint32_t sQh = smem_u32(smem);
    const uint32_t sQl = sQh + 16384;
    const uint32_t sKV = sQl + 16384;       // 2 stages x {Kh,Kl,Vh,Vl} x 8KB

    const int bh = blockIdx.y;
    const int q0 = blockIdx.x * 128;
    const int tid = threadIdx.x;
    const int lane = tid & 31;
    const int warp = tid >> 5;
    const int g = lane >> 2, tig = lane & 3;
    const int wr = warp * 16;
    const size_t tok0 = (size_t)bh * N;

    // Q tile load (group 0 part 1): 128 rows x 128B, h then l
    {
        const __nv_bfloat16* srcs[2] = {qh, ql};
        #pragma unroll
        for (int u = 0; u < 8; u++) {
            const __nv_bfloat16* src = srcs[u >> 2];
            uint32_t dst = (u >> 2) ? sQl : sQh;
            int c = (u & 3) * 256 + tid;
            int row = c >> 3, seg = c & 7;
            cp16(dst + sw128(row * 128 + seg * 16),
                 src + (tok0 + q0 + row) * DH + seg * 8);
        }
    }
    auto load_kv = [&](int t) {
        int kv0 = t * 64;
        uint32_t sbase = sKV + (t & 1) * 32768;
        const __nv_bfloat16* srcs[4] = {kh, kl, vh, vl};
        #pragma unroll
        for (int u = 0; u < 8; u++) {
            const __nv_bfloat16* src = srcs[u >> 1];
            uint32_t dst = sbase + (u >> 1) * 8192;
            int c = (u & 1) * 256 + tid;
            int row = c >> 3, seg = c & 7;
            cp16(dst + sw128(row * 128 + seg * 16),
                 src + (tok0 + kv0 + row) * DH + seg * 8);
        }
        asm volatile("cp.async.commit_group;\n");
    };
    load_kv(0);   // group 0 = Q + KV0

    float o[8][4];
    #pragma unroll
    for (int nt = 0; nt < 8; nt++)
        #pragma unroll
        for (int q = 0; q < 4; q++) o[nt][q] = 0.f;
    float m0r = -1e30f, m1r = -1e30f, l0r = 0.f, l1r = 0.f;

    const int NKV = N / 64;
    for (int t = 0; t < NKV; t++) {
        if (t + 1 < NKV) {
            load_kv(t + 1);
            asm volatile("cp.async.wait_group 1;\n" ::: "memory");
        } else {
            asm volatile("cp.async.wait_group 0;\n" ::: "memory");
        }
        __syncthreads();
        uint32_t sK = sKV + (t & 1) * 32768;       // Kh
        uint32_t sKl = sK + 8192;
        uint32_t sV = sK + 16384;                  // Vh
        uint32_t sVl = sK + 24576;

        // ---- S = Q K^T (3 split terms), s[8 n8-tiles][4]
        float s[8][4];
        #pragma unroll
        for (int nt = 0; nt < 8; nt++)
            #pragma unroll
            for (int q = 0; q < 4; q++) s[nt][q] = 0.f;

        #pragma unroll
        for (int kt = 0; kt < 4; kt++) {
            uint32_t aH[4], aL[4];
            {
                int row = wr + (lane & 15);
                int seg = kt * 2 + (lane >> 4);
                uint32_t off = sw128(row * 128 + seg * 16);
                ldm_x4(aH, sQh + off);
                ldm_x4(aL, sQl + off);
            }
            #pragma unroll
            for (int bn = 0; bn < 4; bn++) {
                int row = bn * 16 + (lane & 7) + ((lane >> 4) << 3);
                int seg = kt * 2 + ((lane >> 3) & 1);
                uint32_t off = sw128(row * 128 + seg * 16);
                uint32_t bH[4], bL[4];
                ldm_x4(bH, sK + off);
                ldm_x4(bL, sKl + off);
                #pragma unroll
                for (int sub = 0; sub < 2; sub++) {
                    int nt = bn * 2 + sub;
                    mma16816(s[nt], aH, &bH[sub * 2]);
                    mma16816(s[nt], aL, &bH[sub * 2]);
                    mma16816(s[nt], aH, &bL[sub * 2]);
                }
            }
        }

        // ---- online softmax (rows g and g+8, warp-local over tig lanes)
        float tm0 = -1e30f, tm1 = -1e30f;
        #pragma unroll
        for (int nt = 0; nt < 8; nt++) {
            tm0 = fmaxf(tm0, fmaxf(s[nt][0], s[nt][1]));
            tm1 = fmaxf(tm1, fmaxf(s[nt][2], s[nt][3]));
        }
        tm0 = fmaxf(tm0, __shfl_xor_sync(0xffffffffu, tm0, 1));
        tm0 = fmaxf(tm0, __shfl_xor_sync(0xffffffffu, tm0, 2));
        tm1 = fmaxf(tm1, __shfl_xor_sync(0xffffffffu, tm1, 1));
        tm1 = fmaxf(tm1, __shfl_xor_sync(0xffffffffu, tm1, 2));
        float mn0 = fmaxf(m0r, tm0), mn1 = fmaxf(m1r, tm1);
        float rs0 = __expf(m0r - mn0), rs1 = __expf(m1r - mn1);
        float ts0 = 0.f, ts1 = 0.f;
        #pragma unroll
        for (int nt = 0; nt < 8; nt++) {
            s[nt][0] = __expf(s[nt][0] - mn0); ts0 += s[nt][0];
            s[nt][1] = __expf(s[nt][1] - mn0); ts0 += s[nt][1];
            s[nt][2] = __expf(s[nt][2] - mn1); ts1 += s[nt][2];
            s[nt][3] = __expf(s[nt][3] - mn1); ts1 += s[nt][3];
        }
        ts0 += __shfl_xor_sync(0xffffffffu, ts0, 1);
        ts0 += __shfl_xor_sync(0xffffffffu, ts0, 2);
        ts1 += __shfl_xor_sync(0xffffffffu, ts1, 1);
        ts1 += __shfl_xor_sync(0xffffffffu, ts1, 2);
        l0r = l0r * rs0 + ts0; m0r = mn0;
        l1r = l1r * rs1 + ts1; m1r = mn1;
        #pragma unroll
        for (int nt = 0; nt < 8; nt++) {
            o[nt][0] *= rs0; o[nt][1] *= rs0;
            o[nt][2] *= rs1; o[nt][3] *= rs1;
        }

        // ---- P fragments (A-operand layout), hi/lo split in registers
        uint32_t ph[4][4], pl[4][4];
        #pragma unroll
        for (int kt = 0; kt < 4; kt++) {
            split_pack(s[2 * kt][0],     s[2 * kt][1],     ph[kt][0], pl[kt][0]);
            split_pack(s[2 * kt][2],     s[2 * kt][3],     ph[kt][1], pl[kt][1]);
            split_pack(s[2 * kt + 1][0], s[2 * kt + 1][1], ph[kt][2], pl[kt][2]);
            split_pack(s[2 * kt + 1][2], s[2 * kt + 1][3], ph[kt][3], pl[kt][3]);
        }

        // ---- O += P V  (PhVh + PlVh + PhVl), V frags via ldmatrix.trans
        #pragma unroll
        for (int kt = 0; kt < 4; kt++) {
            #pragma unroll
            for (int bn = 0; bn < 4; bn++) {
                int mat = lane >> 3, i = lane & 7;
                int row = kt * 16 + (mat & 1) * 8 + i;
                int coloff = (bn * 16 + (mat >> 1) * 8) * 2;
                uint32_t off = sw128(row * 128 + coloff);
                uint32_t bH[4], bL[4];
                ldm_x4_t(bH, sV + off);
                ldm_x4_t(bL, sVl + off);
                #pragma unroll
                for (int sub = 0; sub < 2; sub++) {
                    int nt = bn * 2 + sub;
                    mma16816(o[nt], ph[kt], &bH[sub * 2]);
                    mma16816(o[nt], pl[kt], &bH[sub * 2]);
                    mma16816(o[nt], ph[kt], &bL[sub * 2]);
                }
            }
        }
        __syncthreads();
    }

    // ---- epilogue: divide by l, write fp32 [tok][512]
    const int b = bh >> 3;
    const int hoff = (bh & 7) * DH;
    const float inv0 = 1.f / l0r, inv1 = 1.f / l1r;
    const int row0 = q0 + wr + g;
    float* p0 = ao + (size_t)(b * N + row0) * C + hoff + 2 * tig;
    float* p1 = ao + (size_t)(b * N + row0 + 8) * C + hoff + 2 * tig;
    #pragma unroll
    for (int nt = 0; nt < 8; nt++) {
        *(float2*)(p0 + nt * 8) = make_float2(o[nt][0] * inv0, o[nt][1] * inv0);
        *(float2*)(p1 + nt * 8) = make_float2(o[nt][2] * inv1, o[nt][3] * inv1);
    }
}

// ---------------------------------------------------------------------------

extern "C" void kernel_launch(void* const* d_in, const int* in_sizes, int n_in,
                              void* d_out, int out_size) {
    (void)in_sizes; (void)n_in; (void)out_size;
    const float* x    = (const float*)d_in[0];
    const float* Wqkv = (const float*)d_in[1];
    const float* Wprj = (const float*)d_in[2];
    float* out = (float*)d_out;

    __nv_bfloat16 *pxh, *pxl, *pWqh, *pWql, *pWph, *pWpl, *paoh, *paol;
    __nv_bfloat16 *pqh, *pql, *pkh, *pkl, *pvh, *pvl;
    float *pxn, *paon, *pao;
    cudaGetSymbolAddress((void**)&pxh,  g_xh);
    cudaGetSymbolAddress((void**)&pxl,  g_xl);
    cudaGetSymbolAddress((void**)&pWqh, g_Wqh);
    cudaGetSymbolAddress((void**)&pWql, g_Wql);
    cudaGetSymbolAddress((void**)&pWph, g_Wph);
    cudaGetSymbolAddress((void**)&pWpl, g_Wpl);
    cudaGetSymbolAddress((void**)&paoh, g_aoh);
    cudaGetSymbolAddress((void**)&paol, g_aol);
    cudaGetSymbolAddress((void**)&pqh,  g_qh);
    cudaGetSymbolAddress((void**)&pql,  g_ql);
    cudaGetSymbolAddress((void**)&pkh,  g_kh);
    cudaGetSymbolAddress((void**)&pkl,  g_kl);
    cudaGetSymbolAddress((void**)&pvh,  g_vh);
    cudaGetSymbolAddress((void**)&pvl,  g_vl);
    cudaGetSymbolAddress((void**)&pxn,  g_xnorm);
    cudaGetSymbolAddress((void**)&paon, g_aonorm);
    cudaGetSymbolAddress((void**)&pao,  g_ao);

    cudaFuncSetAttribute(tc_gemm_kernel<0>,
                         cudaFuncAttributeMaxDynamicSharedMemorySize, GEMM_SMEM);
    cudaFuncSetAttribute(tc_gemm_kernel<1>,
                         cudaFuncAttributeMaxDynamicSharedMemorySize, GEMM_SMEM);
    cudaFuncSetAttribute(attn_mma_kernel,
                         cudaFuncAttributeMaxDynamicSharedMemorySize, ATTN_SMEM);

    // 1. prep
    prep_w_kernel<<<QKV_W, 128>>>(Wqkv, pWqh, pWql, 3 * C);
    prep_w_kernel<<<PRJ_W, 128>>>(Wprj, pWph, pWpl, C);
    prep_act_kernel<<<M, 128>>>(x, pxh, pxl, pxn);

    // 2. bcos QKV projection -> bf16 split, head-major q/k/v (q pre-scaled)
    tc_gemm_kernel<1><<<dim3(QKV_W / BN, M / BM), 256, GEMM_SMEM>>>(
        pxh, pxl, pWqh, pWql, pxn, nullptr, 0,
        pqh, pql, pkh, pkl, pvh, pvl);

    // 3. flash attention (mma.sync bf16, split precision)
    attn_mma_kernel<<<dim3(N / 128, B * H), 256, ATTN_SMEM>>>(
        pqh, pql, pkh, pkl, pvh, pvl, pao);

    // 4. prep attention output
    prep_act_kernel<<<M, 128>>>(pao, paoh, paol, paon);

    // 5. bcos output projection -> d_out
    tc_gemm_kernel<0><<<dim3(PRJ_W / BN, M / BM), 256, GEMM_SMEM>>>(
        paoh, paol, pWph, pWpl, paon, out, PRJ_O,
        nullptr, nullptr, nullptr, nullptr, nullptr, nullptr);
}

// round 7
// speedup vs baseline: 11.9391x; 1.0182x over previous
#include <cuda_runtime.h>
#include <cuda_bf16.h>
#include <cstdint>

namespace {
constexpr int B  = 2;
constexpr int N  = 2048;
constexpr int C  = 512;
constexpr int H  = 8;
constexpr int DH = 64;
constexpr int M  = B * N;          // 4096 tokens
constexpr int QKV_W = 3 * C * 2;   // 3072 weight rows
constexpr int PRJ_W = C * 2;       // 1024 weight rows
constexpr int PRJ_O = C;           // 512 fused outputs

constexpr int BM = 128;
constexpr int BN = 128;
constexpr int BK = 64;             // K tile (bf16) = 128 bytes/row
constexpr int NT = 24;             // 3 split phases * (512/64)
constexpr int TILE_BYTES = BM * 128;
constexpr int BUF_BYTES  = 2 * TILE_BYTES;        // A+B per stage (32 KB)
constexpr int GEMM_SMEM  = 3 * BUF_BYTES + 128;   // 3-stage pipeline

constexpr int ATTN_SMEM = 2 * 16384 + 2 * 32768;  // Qh/Ql + 2 KV stages = 96 KB
}

// Scratch (device globals — no allocation allowed)
__device__ __nv_bfloat16 g_xh[(size_t)M * C];
__device__ __nv_bfloat16 g_xl[(size_t)M * C];
__device__ __nv_bfloat16 g_Wqh[(size_t)QKV_W * C];
__device__ __nv_bfloat16 g_Wql[(size_t)QKV_W * C];
__device__ __nv_bfloat16 g_Wph[(size_t)PRJ_W * C];
__device__ __nv_bfloat16 g_Wpl[(size_t)PRJ_W * C];
__device__ __nv_bfloat16 g_aoh[(size_t)M * C];
__device__ __nv_bfloat16 g_aol[(size_t)M * C];
// attention-ready qkv, head-major: [bh][n][64], hi/lo bf16
__device__ __nv_bfloat16 g_qh[(size_t)B * H * N * DH];
__device__ __nv_bfloat16 g_ql[(size_t)B * H * N * DH];
__device__ __nv_bfloat16 g_kh[(size_t)B * H * N * DH];
__device__ __nv_bfloat16 g_kl[(size_t)B * H * N * DH];
__device__ __nv_bfloat16 g_vh[(size_t)B * H * N * DH];
__device__ __nv_bfloat16 g_vl[(size_t)B * H * N * DH];
__device__ float g_xnorm2[M];            // sum of squares of x rows
__device__ float g_aopart[(size_t)H * M]; // per-head partial sumsq of ao rows

// ---------------------------------------------------------------------------
// PTX helpers (compute_103-safe: cp.async, ldmatrix, mma.sync bf16)
// ---------------------------------------------------------------------------
__device__ __forceinline__ uint32_t smem_u32(const void* p) {
    return (uint32_t)__cvta_generic_to_shared(p);
}
__device__ __forceinline__ void cp16(uint32_t s, const void* g) {
    asm volatile("cp.async.cg.shared.global [%0], [%1], 16;\n" :: "r"(s), "l"(g));
}
__device__ __forceinline__ uint32_t sw128(uint32_t off) {
    return off ^ ((off >> 3) & 0x70);
}
__device__ __forceinline__ void ldm_x4(uint32_t* r, uint32_t addr) {
    asm volatile("ldmatrix.sync.aligned.m8n8.x4.shared.b16 {%0,%1,%2,%3}, [%4];"
                 : "=r"(r[0]), "=r"(r[1]), "=r"(r[2]), "=r"(r[3]) : "r"(addr));
}
__device__ __forceinline__ void ldm_x4_t(uint32_t* r, uint32_t addr) {
    asm volatile("ldmatrix.sync.aligned.m8n8.x4.trans.shared.b16 {%0,%1,%2,%3}, [%4];"
                 : "=r"(r[0]), "=r"(r[1]), "=r"(r[2]), "=r"(r[3]) : "r"(addr));
}
__device__ __forceinline__ void mma16816(float* c, const uint32_t* a,
                                         const uint32_t* b) {
    asm volatile(
        "mma.sync.aligned.m16n8k16.row.col.f32.bf16.bf16.f32 "
        "{%0,%1,%2,%3}, {%4,%5,%6,%7}, {%8,%9}, {%0,%1,%2,%3};"
        : "+f"(c[0]), "+f"(c[1]), "+f"(c[2]), "+f"(c[3])
        : "r"(a[0]), "r"(a[1]), "r"(a[2]), "r"(a[3]), "r"(b[0]), "r"(b[1]));
}
__device__ __forceinline__ uint32_t packbf(float lo, float hi) {
    __nv_bfloat162 t = __floats2bfloat162_rn(lo, hi);
    return *(uint32_t*)&t;
}
__device__ __forceinline__ void split_pack(float lo, float hi,
                                           uint32_t& h, uint32_t& l) {
    h = packbf(lo, hi);
    __nv_bfloat162 hv = *(__nv_bfloat162*)&h;
    l = packbf(lo - __bfloat162float(hv.x), hi - __bfloat162float(hv.y));
}

// ---------------------------------------------------------------------------
// prep: per-row sum-of-squares + bf16 hi/lo split (x)
// ---------------------------------------------------------------------------
__global__ void prep_act_kernel(const float* __restrict__ A,
                                __nv_bfloat16* __restrict__ Ah,
                                __nv_bfloat16* __restrict__ Al,
                                float* __restrict__ norm2) {
    int r = blockIdx.x, t = threadIdx.x;
    float4 v = ((const float4*)(A + (size_t)r * C))[t];
    float s = v.x * v.x + v.y * v.y + v.z * v.z + v.w * v.w;
    #pragma unroll
    for (int o = 16; o; o >>= 1) s += __shfl_xor_sync(0xffffffffu, s, o);
    __shared__ float sm[4];
    if ((t & 31) == 0) sm[t >> 5] = s;
    __syncthreads();
    if (t == 0) norm2[r] = sm[0] + sm[1] + sm[2] + sm[3];
    float va[4] = {v.x, v.y, v.z, v.w};
    #pragma unroll
    for (int j = 0; j < 4; j++) {
        __nv_bfloat16 h = __float2bfloat16(va[j]);
        __nv_bfloat16 l = __float2bfloat16(va[j] - __bfloat162float(h));
        Ah[(size_t)r * C + t * 4 + j] = h;
        Al[(size_t)r * C + t * 4 + j] = l;
    }
}

// prep: normalize weight rows, maxout partners ADJACENT (o->2o, o+half->2o+1)
__global__ void prep_w_kernel(const float* __restrict__ W,
                              __nv_bfloat16* __restrict__ Dh,
                              __nv_bfloat16* __restrict__ Dl, int half) {
    int r = blockIdx.x, t = threadIdx.x;
    float4 v = ((const float4*)(W + (size_t)r * C))[t];
    float s = v.x * v.x + v.y * v.y + v.z * v.z + v.w * v.w;
    #pragma unroll
    for (int o = 16; o; o >>= 1) s += __shfl_xor_sync(0xffffffffu, s, o);
    __shared__ float sm[4];
    if ((t & 31) == 0) sm[t >> 5] = s;
    __syncthreads();
    float inv = rsqrtf(sm[0] + sm[1] + sm[2] + sm[3]);
    int dr = (r < half) ? 2 * r : 2 * (r - half) + 1;
    float va[4] = {v.x, v.y, v.z, v.w};
    #pragma unroll
    for (int j = 0; j < 4; j++) {
        float w = va[j] * inv;
        __nv_bfloat16 h = __float2bfloat16(w);
        __nv_bfloat16 l = __float2bfloat16(w - __bfloat162float(h));
        Dh[(size_t)dr * C + t * 4 + j] = h;
        Dl[(size_t)dr * C + t * 4 + j] = l;
    }
}

// ---------------------------------------------------------------------------
// mma.sync bcos GEMM (bf16x3), 3-stage cp.async pipeline, 1 sync/iter.
// MODE 0: proj — norms from 8 per-head partials, fp32 out.
// MODE 1: qkv — norms = x sumsq, bf16 split scatter head-major (q * 0.125).
// ---------------------------------------------------------------------------
template <int MODE>
__global__ __launch_bounds__(256, 2) void tc_gemm_kernel(
    const __nv_bfloat16* __restrict__ Ah, const __nv_bfloat16* __restrict__ Al,
    const __nv_bfloat16* __restrict__ Wh, const __nv_bfloat16* __restrict__ Wl,
    const float* __restrict__ norms, float* __restrict__ out, int nout,
    __nv_bfloat16* __restrict__ qh, __nv_bfloat16* __restrict__ ql,
    __nv_bfloat16* __restrict__ kh, __nv_bfloat16* __restrict__ kl,
    __nv_bfloat16* __restrict__ vh, __nv_bfloat16* __restrict__ vl)
{
    extern __shared__ char smem[];
    const uint32_t tiles = (smem_u32(smem) + 127) & ~127u;
    const int tid = threadIdx.x;
    const int lane = tid & 31;
    const int warp = tid >> 5;
    const int wm = warp >> 2;
    const int wn = warp & 3;
    const int bm = blockIdx.y * BM;
    const int bc = blockIdx.x * BN;

    auto load_tile = [&](int t) {
        int phase = t >> 3;
        int k0 = (t & 7) * BK;
        const __nv_bfloat16* As = (phase == 2) ? Al : Ah;
        const __nv_bfloat16* Ws = (phase == 1) ? Wl : Wh;
        uint32_t ab = tiles + (t % 3) * BUF_BYTES;
        uint32_t bb = ab + TILE_BYTES;
        #pragma unroll
        for (int u = 0; u < 4; u++) {
            int c = tid + u * 256;
            int row = c >> 3, seg = c & 7;
            uint32_t sw = sw128(row * 128 + seg * 16);
            cp16(ab + sw, As + (size_t)(bm + row) * C + k0 + seg * 8);
            cp16(bb + sw, Ws + (size_t)(bc + row) * C + k0 + seg * 8);
        }
        asm volatile("cp.async.commit_group;\n");
    };

    float acc[4][4][4];
    #pragma unroll
    for (int i = 0; i < 4; i++)
        #pragma unroll
        for (int j = 0; j < 4; j++)
            #pragma unroll
            for (int q = 0; q < 4; q++) acc[i][j][q] = 0.f;

    load_tile(0);
    load_tile(1);

    for (int t = 0; t < NT; t++) {
        asm volatile("cp.async.wait_group 1;\n" ::: "memory");
        __syncthreads();
        if (t + 2 < NT) load_tile(t + 2);

        uint32_t ab = tiles + (t % 3) * BUF_BYTES;
        uint32_t bb = ab + TILE_BYTES;

        #pragma unroll
        for (int ks = 0; ks < 4; ks++) {
            uint32_t afrag[4][4], bfrag[2][4];
            #pragma unroll
            for (int mt = 0; mt < 4; mt++) {
                int row = wm * 64 + mt * 16 + (lane & 15);
                int seg = ks * 2 + (lane >> 4);
                ldm_x4(afrag[mt], ab + sw128(row * 128 + seg * 16));
            }
            #pragma unroll
            for (int p = 0; p < 2; p++) {
                int row = wn * 32 + p * 16 + (lane & 7) + ((lane >> 4) << 3);
                int seg = ks * 2 + ((lane >> 3) & 1);
                ldm_x4(bfrag[p], bb + sw128(row * 128 + seg * 16));
            }
            #pragma unroll
            for (int mt = 0; mt < 4; mt++)
                #pragma unroll
                for (int nt = 0; nt < 4; nt++)
                    mma16816(acc[mt][nt], afrag[mt], &bfrag[nt >> 1][(nt & 1) * 2]);
        }
    }

    const float sc = rsqrtf((float)C);
    const int g = lane >> 2, tig = lane & 3;

    // MODE 1: block-uniform destination (64-col span within one section/head)
    __nv_bfloat16 *dsth = nullptr, *dstl = nullptr;
    float qscale = 1.f;
    int hh = 0;
    if (MODE == 1) {
        int colbase = bc >> 1;
        int sect = colbase >> 9;
        hh = (colbase & 511) >> 6;
        if (sect == 0)      { dsth = qh; dstl = ql; qscale = 0.125f; }
        else if (sect == 1) { dsth = kh; dstl = kl; }
        else                { dsth = vh; dstl = vl; }
    }

    #pragma unroll
    for (int mt = 0; mt < 4; mt++) {
        int m0 = bm + wm * 64 + mt * 16;
        int r0 = m0 + g, r1 = m0 + g + 8;
        float inv0, inv1;
        if (MODE == 0) {
            float s0 = 0.f, s1 = 0.f;
            #pragma unroll
            for (int p = 0; p < H; p++) {
                s0 += norms[(size_t)p * M + r0];
                s1 += norms[(size_t)p * M + r1];
            }
            inv0 = sc * rsqrtf(s0);
            inv1 = sc * rsqrtf(s1);
        } else {
            inv0 = sc * rsqrtf(norms[r0]);
            inv1 = sc * rsqrtf(norms[r1]);
        }
        #pragma unroll
        for (int nt = 0; nt < 4; nt++) {
            float v0 = fmaxf(acc[mt][nt][0], acc[mt][nt][1]);
            v0 = v0 * fabsf(v0) * inv0;
            float v1 = fmaxf(acc[mt][nt][2], acc[mt][nt][3]);
            v1 = v1 * fabsf(v1) * inv1;
            if (MODE == 0) {
                int col = (bc >> 1) + wn * 16 + nt * 4 + tig;
                out[(size_t)r0 * nout + col] = v0;
                out[(size_t)r1 * nout + col] = v1;
            } else {
                int d = wn * 16 + nt * 4 + tig;
                v0 *= qscale; v1 *= qscale;
                __nv_bfloat16 h0 = __float2bfloat16(v0);
                __nv_bfloat16 h1 = __float2bfloat16(v1);
                size_t i0 = ((size_t)(((r0 >> 11) << 3) + hh) * N + (r0 & 2047)) * DH + d;
                size_t i1 = ((size_t)(((r1 >> 11) << 3) + hh) * N + (r1 & 2047)) * DH + d;
                dsth[i0] = h0; dstl[i0] = __float2bfloat16(v0 - __bfloat162float(h0));
                dsth[i1] = h1; dstl[i1] = __float2bfloat16(v1 - __bfloat162float(h1));
            }
        }
    }
}

// ---------------------------------------------------------------------------
// Flash attention, mma.sync bf16 split. Block = 128 q-rows of one (b,h).
// Epilogue writes bf16 hi/lo ao directly + per-(head,row) partial sumsq.
// ---------------------------------------------------------------------------
__global__ __launch_bounds__(256, 2) void attn_mma_kernel(
    const __nv_bfloat16* __restrict__ qh, const __nv_bfloat16* __restrict__ ql,
    const __nv_bfloat16* __restrict__ kh, const __nv_bfloat16* __restrict__ kl,
    const __nv_bfloat16* __restrict__ vh, const __nv_bfloat16* __restrict__ vl,
    __nv_bfloat16* __restrict__ aoh, __nv_bfloat16* __restrict__ aol,
    float* __restrict__ aopart)
{
    extern __shared__ char smem[];
    const uint32_t sQh = smem_u32(smem);
    const uint32_t sQl = sQh + 16384;
    const uint32_t sKV = sQl + 16384;       // 2 stages x {Kh,Kl,Vh,Vl} x 8KB

    const int bh = blockIdx.y;
    const int q0 = blockIdx.x * 128;
    const int tid = threadIdx.x;
    const int lane = tid & 31;
    const int warp = tid >> 5;
    const int g = lane >> 2, tig = lane & 3;
    const int wr = warp * 16;
    const size_t tok0 = (size_t)bh * N;

    {
        const __nv_bfloat16* srcs[2] = {qh, ql};
        #pragma unroll
        for (int u = 0; u < 8; u++) {
            const __nv_bfloat16* src = srcs[u >> 2];
            uint32_t dst = (u >> 2) ? sQl : sQh;
            int c = (u & 3) * 256 + tid;
            int row = c >> 3, seg = c & 7;
            cp16(dst + sw128(row * 128 + seg * 16),
                 src + (tok0 + q0 + row) * DH + seg * 8);
        }
    }
    auto load_kv = [&](int t) {
        int kv0 = t * 64;
        uint32_t sbase = sKV + (t & 1) * 32768;
        const __nv_bfloat16* srcs[4] = {kh, kl, vh, vl};
        #pragma unroll
        for (int u = 0; u < 8; u++) {
            const __nv_bfloat16* src = srcs[u >> 1];
            uint32_t dst = sbase + (u >> 1) * 8192;
            int c = (u & 1) * 256 + tid;
            int row = c >> 3, seg = c & 7;
            cp16(dst + sw128(row * 128 + seg * 16),
                 src + (tok0 + kv0 + row) * DH + seg * 8);
        }
        asm volatile("cp.async.commit_group;\n");
    };
    load_kv(0);   // group 0 = Q + KV0

    float o[8][4];
    #pragma unroll
    for (int nt = 0; nt < 8; nt++)
        #pragma unroll
        for (int q = 0; q < 4; q++) o[nt][q] = 0.f;
    float m0r = -1e30f, m1r = -1e30f, l0r = 0.f, l1r = 0.f;

    const int NKV = N / 64;
    for (int t = 0; t < NKV; t++) {
        if (t + 1 < NKV) {
            load_kv(t + 1);
            asm volatile("cp.async.wait_group 1;\n" ::: "memory");
        } else {
            asm volatile("cp.async.wait_group 0;\n" ::: "memory");
        }
        __syncthreads();
        uint32_t sK = sKV + (t & 1) * 32768;       // Kh
        uint32_t sKl = sK + 8192;
        uint32_t sV = sK + 16384;                  // Vh
        uint32_t sVl = sK + 24576;

        // ---- S = Q K^T (3 split terms)
        float s[8][4];
        #pragma unroll
        for (int nt = 0; nt < 8; nt++)
            #pragma unroll
            for (int q = 0; q < 4; q++) s[nt][q] = 0.f;

        #pragma unroll
        for (int kt = 0; kt < 4; kt++) {
            uint32_t aH[4], aL[4];
            {
                int row = wr + (lane & 15);
                int seg = kt * 2 + (lane >> 4);
                uint32_t off = sw128(row * 128 + seg * 16);
                ldm_x4(aH, sQh + off);
                ldm_x4(aL, sQl + off);
            }
            #pragma unroll
            for (int bn = 0; bn < 4; bn++) {
                int row = bn * 16 + (lane & 7) + ((lane >> 4) << 3);
                int seg = kt * 2 + ((lane >> 3) & 1);
                uint32_t off = sw128(row * 128 + seg * 16);
                uint32_t bH[4], bL[4];
                ldm_x4(bH, sK + off);
                ldm_x4(bL, sKl + off);
                #pragma unroll
                for (int sub = 0; sub < 2; sub++) {
                    int nt = bn * 2 + sub;
                    mma16816(s[nt], aH, &bH[sub * 2]);
                    mma16816(s[nt], aL, &bH[sub * 2]);
                    mma16816(s[nt], aH, &bL[sub * 2]);
                }
            }
        }

        // ---- online softmax (rows g and g+8, warp-local over tig lanes)
        float tm0 = -1e30f, tm1 = -1e30f;
        #pragma unroll
        for (int nt = 0; nt < 8; nt++) {
            tm0 = fmaxf(tm0, fmaxf(s[nt][0], s[nt][1]));
            tm1 = fmaxf(tm1, fmaxf(s[nt][2], s[nt][3]));
        }
        tm0 = fmaxf(tm0, __shfl_xor_sync(0xffffffffu, tm0, 1));
        tm0 = fmaxf(tm0, __shfl_xor_sync(0xffffffffu, tm0, 2));
        tm1 = fmaxf(tm1, __shfl_xor_sync(0xffffffffu, tm1, 1));
        tm1 = fmaxf(tm1, __shfl_xor_sync(0xffffffffu, tm1, 2));
        float mn0 = fmaxf(m0r, tm0), mn1 = fmaxf(m1r, tm1);
        float rs0 = __expf(m0r - mn0), rs1 = __expf(m1r - mn1);
        float ts0 = 0.f, ts1 = 0.f;
        #pragma unroll
        for (int nt = 0; nt < 8; nt++) {
            s[nt][0] = __expf(s[nt][0] - mn0); ts0 += s[nt][0];
            s[nt][1] = __expf(s[nt][1] - mn0); ts0 += s[nt][1];
            s[nt][2] = __expf(s[nt][2] - mn1); ts1 += s[nt][2];
            s[nt][3] = __expf(s[nt][3] - mn1); ts1 += s[nt][3];
        }
        ts0 += __shfl_xor_sync(0xffffffffu, ts0, 1);
        ts0 += __shfl_xor_sync(0xffffffffu, ts0, 2);
        ts1 += __shfl_xor_sync(0xffffffffu, ts1, 1);
        ts1 += __shfl_xor_sync(0xffffffffu, ts1, 2);
        l0r = l0r * rs0 + ts0; m0r = mn0;
        l1r = l1r * rs1 + ts1; m1r = mn1;
        #pragma unroll
        for (int nt = 0; nt < 8; nt++) {
            o[nt][0] *= rs0; o[nt][1] *= rs0;
            o[nt][2] *= rs1; o[nt][3] *= rs1;
        }

        // ---- P fragments (A-operand layout), hi/lo split in registers
        uint32_t ph[4][4], pl[4][4];
        #pragma unroll
        for (int kt = 0; kt < 4; kt++) {
            split_pack(s[2 * kt][0],     s[2 * kt][1],     ph[kt][0], pl[kt][0]);
            split_pack(s[2 * kt][2],     s[2 * kt][3],     ph[kt][1], pl[kt][1]);
            split_pack(s[2 * kt + 1][0], s[2 * kt + 1][1], ph[kt][2], pl[kt][2]);
            split_pack(s[2 * kt + 1][2], s[2 * kt + 1][3], ph[kt][3], pl[kt][3]);
        }

        // ---- O += P V  (PhVh + PlVh + PhVl), V frags via ldmatrix.trans
        #pragma unroll
        for (int kt = 0; kt < 4; kt++) {
            #pragma unroll
            for (int bn = 0; bn < 4; bn++) {
                int mat = lane >> 3, i = lane & 7;
                int row = kt * 16 + (mat & 1) * 8 + i;
                int coloff = (bn * 16 + (mat >> 1) * 8) * 2;
                uint32_t off = sw128(row * 128 + coloff);
                uint32_t bH[4], bL[4];
                ldm_x4_t(bH, sV + off);
                ldm_x4_t(bL, sVl + off);
                #pragma unroll
                for (int sub = 0; sub < 2; sub++) {
                    int nt = bn * 2 + sub;
                    mma16816(o[nt], ph[kt], &bH[sub * 2]);
                    mma16816(o[nt], pl[kt], &bH[sub * 2]);
                    mma16816(o[nt], ph[kt], &bL[sub * 2]);
                }
            }
        }
        __syncthreads();
    }

    // ---- epilogue: /l, bf16 hi/lo split, partial sumsq per (head,row)
    const int b = bh >> 3;
    const int h = bh & 7;
    const int hoff = h * DH;
    const float inv0 = 1.f / l0r, inv1 = 1.f / l1r;
    const int row0 = q0 + wr + g;
    const size_t base0 = (size_t)(b * N + row0) * C + hoff + 2 * tig;
    const size_t base1 = (size_t)(b * N + row0 + 8) * C + hoff + 2 * tig;
    float ss0 = 0.f, ss1 = 0.f;
    #pragma unroll
    for (int nt = 0; nt < 8; nt++) {
        float a0 = o[nt][0] * inv0, a1 = o[nt][1] * inv0;
        float b0 = o[nt][2] * inv1, b1 = o[nt][3] * inv1;
        ss0 += a0 * a0 + a1 * a1;
        ss1 += b0 * b0 + b1 * b1;
        uint32_t h0, l0, h1, l1;
        split_pack(a0, a1, h0, l0);
        split_pack(b0, b1, h1, l1);
        *(uint32_t*)(aoh + base0 + nt * 8) = h0;
        *(uint32_t*)(aol + base0 + nt * 8) = l0;
        *(uint32_t*)(aoh + base1 + nt * 8) = h1;
        *(uint32_t*)(aol + base1 + nt * 8) = l1;
    }
    ss0 += __shfl_xor_sync(0xffffffffu, ss0, 1);
    ss0 += __shfl_xor_sync(0xffffffffu, ss0, 2);
    ss1 += __shfl_xor_sync(0xffffffffu, ss1, 1);
    ss1 += __shfl_xor_sync(0xffffffffu, ss1, 2);
    if (tig == 0) {
        aopart[(size_t)h * M + b * N + row0]     = ss0;
        aopart[(size_t)h * M + b * N + row0 + 8] = ss1;
    }
}

// ---------------------------------------------------------------------------

extern "C" void kernel_launch(void* const* d_in, const int* in_sizes, int n_in,
                              void* d_out, int out_size) {
    (void)in_sizes; (void)n_in; (void)out_size;
    const float* x    = (const float*)d_in[0];
    const float* Wqkv = (const float*)d_in[1];
    const float* Wprj = (const float*)d_in[2];
    float* out = (float*)d_out;

    __nv_bfloat16 *pxh, *pxl, *pWqh, *pWql, *pWph, *pWpl, *paoh, *paol;
    __nv_bfloat16 *pqh, *pql, *pkh, *pkl, *pvh, *pvl;
    float *pxn2, *papart;
    cudaGetSymbolAddress((void**)&pxh,  g_xh);
    cudaGetSymbolAddress((void**)&pxl,  g_xl);
    cudaGetSymbolAddress((void**)&pWqh, g_Wqh);
    cudaGetSymbolAddress((void**)&pWql, g_Wql);
    cudaGetSymbolAddress((void**)&pWph, g_Wph);
    cudaGetSymbolAddress((void**)&pWpl, g_Wpl);
    cudaGetSymbolAddress((void**)&paoh, g_aoh);
    cudaGetSymbolAddress((void**)&paol, g_aol);
    cudaGetSymbolAddress((void**)&pqh,  g_qh);
    cudaGetSymbolAddress((void**)&pql,  g_ql);
    cudaGetSymbolAddress((void**)&pkh,  g_kh);
    cudaGetSymbolAddress((void**)&pkl,  g_kl);
    cudaGetSymbolAddress((void**)&pvh,  g_vh);
    cudaGetSymbolAddress((void**)&pvl,  g_vl);
    cudaGetSymbolAddress((void**)&pxn2, g_xnorm2);
    cudaGetSymbolAddress((void**)&papart, g_aopart);

    cudaFuncSetAttribute(tc_gemm_kernel<0>,
                         cudaFuncAttributeMaxDynamicSharedMemorySize, GEMM_SMEM);
    cudaFuncSetAttribute(tc_gemm_kernel<1>,
                         cudaFuncAttributeMaxDynamicSharedMemorySize, GEMM_SMEM);
    cudaFuncSetAttribute(attn_mma_kernel,
                         cudaFuncAttributeMaxDynamicSharedMemorySize, ATTN_SMEM);

    // 1. prep
    prep_w_kernel<<<QKV_W, 128>>>(Wqkv, pWqh, pWql, 3 * C);
    prep_w_kernel<<<PRJ_W, 128>>>(Wprj, pWph, pWpl, C);
    prep_act_kernel<<<M, 128>>>(x, pxh, pxl, pxn2);

    // 2. bcos QKV projection -> bf16 split, head-major q/k/v (q pre-scaled)
    tc_gemm_kernel<1><<<dim3(QKV_W / BN, M / BM), 256, GEMM_SMEM>>>(
        pxh, pxl, pWqh, pWql, pxn2, nullptr, 0,
        pqh, pql, pkh, pkl, pvh, pvl);

    // 3. flash attention -> bf16 split ao + per-head partial norms
    attn_mma_kernel<<<dim3(N / 128, B * H), 256, ATTN_SMEM>>>(
        pqh, pql, pkh, pkl, pvh, pvl, paoh, paol, papart);

    // 4. bcos output projection -> d_out (norms summed from partials)
    tc_gemm_kernel<0><<<dim3(PRJ_W / BN, M / BM), 256, GEMM_SMEM>>>(
        paoh, paol, pWph, pWpl, papart, out, PRJ_O,
        nullptr, nullptr, nullptr, nullptr, nullptr, nullptr);
}